// round 1
// baseline (speedup 1.0000x reference)
#include <cuda_runtime.h>

#define SQ 2048
#define DM 1024
#define NH 16
#define BB 2
#define MR (BB*SQ)   // 4096 rows

// Scratch (allocation-free rule: __device__ globals)
static __device__ float g_q[MR*DM];
static __device__ float g_k[MR*DM];
static __device__ float g_v[MR*DM];
static __device__ float g_ao[MR*DM];

// ---------------------------------------------------------------------------
// Tiled fp32 GEMM: C[4096x1024] = A[4096x1024] @ W + bias
// WMODE 0: W plain row-major [K][N]
// WMODE 1: W = stacked per-head [H][D][64]; W(k, c) = W[(c>>6)][k][(c&63)]
// Tile 128x128x16, 256 threads, 8x8 per thread.
// ---------------------------------------------------------------------------
template<int WMODE>
__global__ __launch_bounds__(256) void gemm128(const float* __restrict__ A,
                                               const float* __restrict__ W,
                                               const float* __restrict__ bias,
                                               float* __restrict__ C)
{
    __shared__ float As[16][132];
    __shared__ float Bs[16][132];
    const int tid = threadIdx.x;
    const int m0 = blockIdx.y * 128;
    const int n0 = blockIdx.x * 128;
    const int ty = tid >> 4, tx = tid & 15;

    float acc[8][8];
#pragma unroll
    for (int r = 0; r < 8; r++)
#pragma unroll
        for (int c = 0; c < 8; c++) acc[r][c] = 0.f;

    for (int k0 = 0; k0 < DM; k0 += 16) {
#pragma unroll
        for (int j = 0; j < 8; j++) {
            int i = tid + j * 256;              // 2048 elems
            int kk = i & 15, row = i >> 4;
            As[kk][row] = A[(m0 + row) * DM + k0 + kk];
        }
#pragma unroll
        for (int j = 0; j < 8; j++) {
            int i = tid + j * 256;
            int col = i & 127, kk = i >> 7;
            int c = n0 + col;
            float w;
            if (WMODE) w = W[((c >> 6) * DM + (k0 + kk)) * 64 + (c & 63)];
            else       w = W[(k0 + kk) * DM + c];
            Bs[kk][col] = w;
        }
        __syncthreads();
#pragma unroll
        for (int kk = 0; kk < 16; kk++) {
            float a[8], b[8];
            *(float4*)&a[0] = *(const float4*)&As[kk][ty * 8];
            *(float4*)&a[4] = *(const float4*)&As[kk][ty * 8 + 4];
            *(float4*)&b[0] = *(const float4*)&Bs[kk][tx * 8];
            *(float4*)&b[4] = *(const float4*)&Bs[kk][tx * 8 + 4];
#pragma unroll
            for (int r = 0; r < 8; r++)
#pragma unroll
                for (int c = 0; c < 8; c++)
                    acc[r][c] += a[r] * b[c];
        }
        __syncthreads();
    }

#pragma unroll
    for (int r = 0; r < 8; r++) {
        float o[8];
#pragma unroll
        for (int c = 0; c < 8; c++) o[c] = acc[r][c] + bias[n0 + tx * 8 + c];
        float* dst = &C[(m0 + ty * 8 + r) * DM + n0 + tx * 8];
        *(float4*)dst       = *(float4*)&o[0];
        *(float4*)(dst + 4) = *(float4*)&o[4];
    }
}

// ---------------------------------------------------------------------------
// Fused batch-softmax attention.
// softmax over batch axis (B=2):  attn0 = sigmoid(d), attn1 = 1 - sigmoid(d)
// with d = (q0.k0 - q1.k1)/8 = dot(Qt[s], Kt[t])/8, Qt=[q0|q1], Kt=[k0|-k1].
// One CTA per (64-row s-tile, head). Loops over all t tiles of 64.
// out layout: [B, S, H*64] (concat layout) -> feeds final GEMM directly.
// ---------------------------------------------------------------------------
__global__ __launch_bounds__(256) void attn64(const float* __restrict__ qb,
                                              const float* __restrict__ kb,
                                              const float* __restrict__ vb,
                                              float* __restrict__ out)
{
    extern __shared__ float sm[];
    float* sQ  = sm;                 // [128][68]  Qt, kk-major
    float* sKV = sm + 128 * 68;      // Kt [128][68]  /  V [64][132]
    float* sP  = sKV + 128 * 68;     // [t=64][68]  sigmoid(d)
    float* sPc = sP + 64 * 68;       // [t=64][68]  1 - sigmoid(d)

    const int tid = threadIdx.x;
    const int s0 = blockIdx.x * 64;
    const int h  = blockIdx.y;
    const int ty = tid >> 4, tx = tid & 15;
    const int hoff = h * 64;

    // Load Qt tile [64 s][128 kk]: kk<64 -> q0, kk>=64 -> q1 (coalesced over kk)
    for (int i = tid; i < 64 * 128; i += 256) {
        int kk = i & 127, s = i >> 7;
        int b = kk >> 6;
        sQ[kk * 68 + s] = qb[(b * SQ + s0 + s) * DM + hoff + (kk & 63)];
    }

    float acc[4][8];
#pragma unroll
    for (int r = 0; r < 4; r++)
#pragma unroll
        for (int c = 0; c < 8; c++) acc[r][c] = 0.f;

    for (int t0 = 0; t0 < SQ; t0 += 64) {
        __syncthreads();   // prev PV done with sKV / sP
        // Load Kt tile [64 t][128 kk], negating the k1 half
        for (int i = tid; i < 64 * 128; i += 256) {
            int kk = i & 127, t = i >> 7;
            int b = kk >> 6;
            float val = kb[(b * SQ + t0 + t) * DM + hoff + (kk & 63)];
            sKV[kk * 68 + t] = b ? -val : val;
        }
        __syncthreads();

        // Score GEMM: 64x64, K=128, 4x4 per thread
        float sc[4][4];
#pragma unroll
        for (int r = 0; r < 4; r++)
#pragma unroll
            for (int c = 0; c < 4; c++) sc[r][c] = 0.f;
#pragma unroll 8
        for (int kk = 0; kk < 128; kk++) {
            float4 a  = *(const float4*)&sQ [kk * 68 + ty * 4];
            float4 b4 = *(const float4*)&sKV[kk * 68 + tx * 4];
            float av[4] = {a.x, a.y, a.z, a.w};
            float bv4[4] = {b4.x, b4.y, b4.z, b4.w};
#pragma unroll
            for (int r = 0; r < 4; r++)
#pragma unroll
                for (int c = 0; c < 4; c++)
                    sc[r][c] += av[r] * bv4[c];
        }

        // sigmoid, store transposed P[t][s] and complement
#pragma unroll
        for (int c = 0; c < 4; c++)
#pragma unroll
            for (int r = 0; r < 4; r++) {
                float p = 1.f / (1.f + __expf(-0.125f * sc[r][c]));
                sP [(tx * 4 + c) * 68 + ty * 4 + r] = p;
                sPc[(tx * 4 + c) * 68 + ty * 4 + r] = 1.f - p;
            }
        __syncthreads();   // scores done reading sKV(K); P written

        // Load V tile [64 t][128 c]: c<64 -> v0, c>=64 -> v1
        for (int i = tid; i < 64 * 128; i += 256) {
            int c = i & 127, t = i >> 7;
            int b = c >> 6;
            sKV[t * 132 + c] = vb[(b * SQ + t0 + t) * DM + hoff + (c & 63)];
        }
        __syncthreads();

        // PV GEMM: out tile [64 s][128 c], K=64, 4x8 per thread.
        // cols 0..63 use P (batch 0), cols 64..127 use 1-P (batch 1).
        const float* Pb = (tx < 8) ? sP : sPc;
#pragma unroll 8
        for (int kk = 0; kk < 64; kk++) {
            float4 a  = *(const float4*)&Pb[kk * 68 + ty * 4];
            float4 b0 = *(const float4*)&sKV[kk * 132 + tx * 8];
            float4 b1 = *(const float4*)&sKV[kk * 132 + tx * 8 + 4];
            float av[4] = {a.x, a.y, a.z, a.w};
            float bv8[8] = {b0.x, b0.y, b0.z, b0.w, b1.x, b1.y, b1.z, b1.w};
#pragma unroll
            for (int r = 0; r < 4; r++)
#pragma unroll
                for (int c = 0; c < 8; c++)
                    acc[r][c] += av[r] * bv8[c];
        }
    }

    // Write [B, S, H*64] concat layout
    const int b  = tx >> 3;
    const int cb = (tx & 7) * 8;
#pragma unroll
    for (int r = 0; r < 4; r++) {
        float* dst = &out[(b * SQ + s0 + ty * 4 + r) * DM + hoff + cb];
        float4 o0 = {acc[r][0], acc[r][1], acc[r][2], acc[r][3]};
        float4 o1 = {acc[r][4], acc[r][5], acc[r][6], acc[r][7]};
        *(float4*)dst       = o0;
        *(float4*)(dst + 4) = o1;
    }
}

// ---------------------------------------------------------------------------
extern "C" void kernel_launch(void* const* d_in, const int* in_sizes, int n_in,
                              void* d_out, int out_size)
{
    const float* query = (const float*)d_in[0];
    const float* key   = (const float*)d_in[1];
    const float* value = (const float*)d_in[2];
    const float* Wq = (const float*)d_in[3];
    const float* bq = (const float*)d_in[4];
    const float* Wk = (const float*)d_in[5];
    const float* bk = (const float*)d_in[6];
    const float* Wv = (const float*)d_in[7];
    const float* bv = (const float*)d_in[8];
    const float* Wo = (const float*)d_in[9];
    const float* bo = (const float*)d_in[10];
    float* out = (float*)d_out;

    float *qp, *kp, *vp, *aop;
    cudaGetSymbolAddress((void**)&qp,  g_q);
    cudaGetSymbolAddress((void**)&kp,  g_k);
    cudaGetSymbolAddress((void**)&vp,  g_v);
    cudaGetSymbolAddress((void**)&aop, g_ao);

    const int ATTN_SMEM = (128 * 68 * 2 + 64 * 68 * 2) * 4;  // 104448 B
    cudaFuncSetAttribute(attn64, cudaFuncAttributeMaxDynamicSharedMemorySize,
                         ATTN_SMEM);

    dim3 blk(256);
    dim3 gg(DM / 128, MR / 128);            // (8, 32)

    gemm128<1><<<gg, blk>>>(query, Wq, bq, qp);
    gemm128<1><<<gg, blk>>>(key,   Wk, bk, kp);
    gemm128<1><<<gg, blk>>>(value, Wv, bv, vp);

    attn64<<<dim3(SQ / 64, NH), blk, ATTN_SMEM>>>(qp, kp, vp, aop);

    gemm128<0><<<gg, blk>>>(aop, Wo, bo, out);
}

// round 2
// speedup vs baseline: 1.0134x; 1.0134x over previous
#include <cuda_runtime.h>

#define SQ 2048
#define DM 1024
#define NH 16
#define BB 2
#define MR (BB*SQ)   // 4096 rows

// Scratch (allocation-free rule: __device__ globals)
static __device__ float g_q[MR*DM];
static __device__ float g_k[MR*DM];
static __device__ float g_v[MR*DM];
static __device__ float g_ao[MR*DM];

// ---------------------------------------------------------------------------
// Tiled fp32 GEMM: C[4096x1024] = A[4096x1024] @ W + bias
// WMODE 0: W plain row-major [K][N]
// WMODE 1: W = stacked per-head [H][D][64]; W(k, c) = W[(c>>6)][k][(c&63)]
// Tile 128x128x16, 256 threads, 8x8 per thread.
// ---------------------------------------------------------------------------
template<int WMODE>
__global__ __launch_bounds__(256) void gemm128(const float* __restrict__ A,
                                               const float* __restrict__ W,
                                               const float* __restrict__ bias,
                                               float* __restrict__ C)
{
    __shared__ float As[16][132];
    __shared__ float Bs[16][132];
    const int tid = threadIdx.x;
    const int m0 = blockIdx.y * 128;
    const int n0 = blockIdx.x * 128;
    const int ty = tid >> 4, tx = tid & 15;

    float acc[8][8];
#pragma unroll
    for (int r = 0; r < 8; r++)
#pragma unroll
        for (int c = 0; c < 8; c++) acc[r][c] = 0.f;

    for (int k0 = 0; k0 < DM; k0 += 16) {
#pragma unroll
        for (int j = 0; j < 8; j++) {
            int i = tid + j * 256;              // 2048 elems
            int kk = i & 15, row = i >> 4;
            As[kk][row] = A[(m0 + row) * DM + k0 + kk];
        }
#pragma unroll
        for (int j = 0; j < 8; j++) {
            int i = tid + j * 256;
            int col = i & 127, kk = i >> 7;
            int c = n0 + col;
            float w;
            if (WMODE) w = W[((c >> 6) * DM + (k0 + kk)) * 64 + (c & 63)];
            else       w = W[(k0 + kk) * DM + c];
            Bs[kk][col] = w;
        }
        __syncthreads();
#pragma unroll
        for (int kk = 0; kk < 16; kk++) {
            float a[8], b[8];
            *(float4*)&a[0] = *(const float4*)&As[kk][ty * 8];
            *(float4*)&a[4] = *(const float4*)&As[kk][ty * 8 + 4];
            *(float4*)&b[0] = *(const float4*)&Bs[kk][tx * 8];
            *(float4*)&b[4] = *(const float4*)&Bs[kk][tx * 8 + 4];
#pragma unroll
            for (int r = 0; r < 8; r++)
#pragma unroll
                for (int c = 0; c < 8; c++)
                    acc[r][c] += a[r] * b[c];
        }
        __syncthreads();
    }

#pragma unroll
    for (int r = 0; r < 8; r++) {
        float o[8];
#pragma unroll
        for (int c = 0; c < 8; c++) o[c] = acc[r][c] + bias[n0 + tx * 8 + c];
        float* dst = &C[(m0 + ty * 8 + r) * DM + n0 + tx * 8];
        *(float4*)dst       = *(float4*)&o[0];
        *(float4*)(dst + 4) = *(float4*)&o[4];
    }
}

// ---------------------------------------------------------------------------
// Fused batch-softmax attention.
// softmax over batch axis (B=2):  attn0 = sigmoid(d), attn1 = 1 - sigmoid(d)
// with d = (q0.k0 - q1.k1)/8 = dot(Qt[s], Kt[t])/8, Qt=[q0|q1], Kt=[k0|-k1].
// One CTA per (64-row s-tile, head). Loops over all t tiles of 64.
// out layout: [B, S, H*64] (concat layout) -> feeds final GEMM directly.
// ---------------------------------------------------------------------------
__global__ __launch_bounds__(256) void attn64(const float* __restrict__ qb,
                                              const float* __restrict__ kb,
                                              const float* __restrict__ vb,
                                              float* __restrict__ out)
{
    extern __shared__ float sm[];
    float* sQ  = sm;                 // [128][68]  Qt, kk-major
    float* sKV = sm + 128 * 68;      // Kt [128][68]  /  V [64][132]
    float* sP  = sKV + 128 * 68;     // [t=64][68]  sigmoid(d)
    float* sPc = sP + 64 * 68;       // [t=64][68]  1 - sigmoid(d)

    const int tid = threadIdx.x;
    const int s0 = blockIdx.x * 64;
    const int h  = blockIdx.y;
    const int ty = tid >> 4, tx = tid & 15;
    const int hoff = h * 64;

    // Load Qt tile [64 s][128 kk]: kk<64 -> q0, kk>=64 -> q1 (coalesced over kk)
    for (int i = tid; i < 64 * 128; i += 256) {
        int kk = i & 127, s = i >> 7;
        int b = kk >> 6;
        sQ[kk * 68 + s] = qb[(b * SQ + s0 + s) * DM + hoff + (kk & 63)];
    }

    float acc[4][8];
#pragma unroll
    for (int r = 0; r < 4; r++)
#pragma unroll
        for (int c = 0; c < 8; c++) acc[r][c] = 0.f;

    for (int t0 = 0; t0 < SQ; t0 += 64) {
        __syncthreads();   // prev PV done with sKV / sP
        // Load Kt tile [64 t][128 kk], negating the k1 half
        for (int i = tid; i < 64 * 128; i += 256) {
            int kk = i & 127, t = i >> 7;
            int b = kk >> 6;
            float val = kb[(b * SQ + t0 + t) * DM + hoff + (kk & 63)];
            sKV[kk * 68 + t] = b ? -val : val;
        }
        __syncthreads();

        // Score GEMM: 64x64, K=128, 4x4 per thread
        float sc[4][4];
#pragma unroll
        for (int r = 0; r < 4; r++)
#pragma unroll
            for (int c = 0; c < 4; c++) sc[r][c] = 0.f;
#pragma unroll 8
        for (int kk = 0; kk < 128; kk++) {
            float4 a  = *(const float4*)&sQ [kk * 68 + ty * 4];
            float4 b4 = *(const float4*)&sKV[kk * 68 + tx * 4];
            float av[4] = {a.x, a.y, a.z, a.w};
            float bv4[4] = {b4.x, b4.y, b4.z, b4.w};
#pragma unroll
            for (int r = 0; r < 4; r++)
#pragma unroll
                for (int c = 0; c < 4; c++)
                    sc[r][c] += av[r] * bv4[c];
        }

        // sigmoid, store transposed P[t][s] and complement
#pragma unroll
        for (int c = 0; c < 4; c++)
#pragma unroll
            for (int r = 0; r < 4; r++) {
                float p = 1.f / (1.f + __expf(-0.125f * sc[r][c]));
                sP [(tx * 4 + c) * 68 + ty * 4 + r] = p;
                sPc[(tx * 4 + c) * 68 + ty * 4 + r] = 1.f - p;
            }
        __syncthreads();   // scores done reading sKV(K); P written

        // Load V tile [64 t][128 c]: c<64 -> v0, c>=64 -> v1
        for (int i = tid; i < 64 * 128; i += 256) {
            int c = i & 127, t = i >> 7;
            int b = c >> 6;
            sKV[t * 132 + c] = vb[(b * SQ + t0 + t) * DM + hoff + (c & 63)];
        }
        __syncthreads();

        // PV GEMM: out tile [64 s][128 c], K=64, 4x8 per thread.
        // cols 0..63 use P (batch 0), cols 64..127 use 1-P (batch 1).
        const float* Pb = (tx < 8) ? sP : sPc;
#pragma unroll 8
        for (int kk = 0; kk < 64; kk++) {
            float4 a  = *(const float4*)&Pb[kk * 68 + ty * 4];
            float4 b0 = *(const float4*)&sKV[kk * 132 + tx * 8];
            float4 b1 = *(const float4*)&sKV[kk * 132 + tx * 8 + 4];
            float av[4] = {a.x, a.y, a.z, a.w};
            float bv8[8] = {b0.x, b0.y, b0.z, b0.w, b1.x, b1.y, b1.z, b1.w};
#pragma unroll
            for (int r = 0; r < 4; r++)
#pragma unroll
                for (int c = 0; c < 8; c++)
                    acc[r][c] += av[r] * bv8[c];
        }
    }

    // Write [B, S, H*64] concat layout
    const int b  = tx >> 3;
    const int cb = (tx & 7) * 8;
#pragma unroll
    for (int r = 0; r < 4; r++) {
        float* dst = &out[(b * SQ + s0 + ty * 4 + r) * DM + hoff + cb];
        float4 o0 = {acc[r][0], acc[r][1], acc[r][2], acc[r][3]};
        float4 o1 = {acc[r][4], acc[r][5], acc[r][6], acc[r][7]};
        *(float4*)dst       = o0;
        *(float4*)(dst + 4) = o1;
    }
}

// ---------------------------------------------------------------------------
extern "C" void kernel_launch(void* const* d_in, const int* in_sizes, int n_in,
                              void* d_out, int out_size)
{
    const float* query = (const float*)d_in[0];
    const float* key   = (const float*)d_in[1];
    const float* value = (const float*)d_in[2];
    const float* Wq = (const float*)d_in[3];
    const float* bq = (const float*)d_in[4];
    const float* Wk = (const float*)d_in[5];
    const float* bk = (const float*)d_in[6];
    const float* Wv = (const float*)d_in[7];
    const float* bv = (const float*)d_in[8];
    const float* Wo = (const float*)d_in[9];
    const float* bo = (const float*)d_in[10];
    float* out = (float*)d_out;

    float *qp, *kp, *vp, *aop;
    cudaGetSymbolAddress((void**)&qp,  g_q);
    cudaGetSymbolAddress((void**)&kp,  g_k);
    cudaGetSymbolAddress((void**)&vp,  g_v);
    cudaGetSymbolAddress((void**)&aop, g_ao);

    const int ATTN_SMEM = (128 * 68 * 2 + 64 * 68 * 2) * 4;  // 104448 B
    cudaFuncSetAttribute(attn64, cudaFuncAttributeMaxDynamicSharedMemorySize,
                         ATTN_SMEM);

    dim3 blk(256);
    dim3 gg(DM / 128, MR / 128);            // (8, 32)

    gemm128<1><<<gg, blk>>>(query, Wq, bq, qp);
    gemm128<1><<<gg, blk>>>(key,   Wk, bk, kp);
    gemm128<1><<<gg, blk>>>(value, Wv, bv, vp);

    attn64<<<dim3(SQ / 64, NH), blk, ATTN_SMEM>>>(qp, kp, vp, aop);

    gemm128<0><<<gg, blk>>>(aop, Wo, bo, out);
}